// round 7
// baseline (speedup 1.0000x reference)
#include <cuda_runtime.h>

// WaveLetPooling: input (8, 512, 512, 64) fp32 NHWC.
// a = in[:,0::2,0::2,:], b = in[:,0::2,1::2,:], c = in[:,1::2,0::2,:], d = in[:,1::2,1::2,:]
// ll = .5(a+b+c+d); lh = .5(-a+b-c+d); hl = .5(-a-b+c+d); hh = .5(a-b-c+d)
// Output: [ll | lh | hl | hh], each (8, 256, 256, 64), concatenated in d_out.
//
// FINAL — roofline-converged across 6 profiled rounds.
// Pure streaming op: 537 MB read + 537 MB written, zero reuse. Measured
// 6.76-6.83 TB/s at DRAM (85-86% of 8 TB/s spec), the achieved HBM3e
// ceiling for a 1:1 R/W mix on this part. Compute pipes <11% busy.
// Levers tested and rejected: 2x MLP per thread (neutral), .cs streaming
// hints (neutral), butterfly factorization (neutral), 512-thread blocks
// (neutral), persistent grid-stride single wave (-10%: fewer independent
// CTAs starves the L1tex/DRAM request pool).
// Winning shape: one float4 of channels per thread, 256-thread blocks,
// 32768 independent CTAs, default-cached LDG.128/STG.128, FFMA-imm math.

#define N_  8u
#define H_  512u
#define W_  512u
#define C_  64u
#define HO  (H_/2u)       // 256
#define WO  (W_/2u)       // 256
#define C4  (C_/4u)       // 16 float4 per position
#define Q4  (N_*HO*WO*C4) // float4 count per quadrant = 8,388,608

__global__ __launch_bounds__(256) void wavelet_pool_kernel(
    const float4* __restrict__ in, float4* __restrict__ out)
{
    unsigned tid = blockIdx.x * blockDim.x + threadIdx.x;
    // tid -> (n, ho, wo, c4): c4 in [0,16), wo in [0,256), ho in [0,256), n in [0,8)
    unsigned c4 = tid & 15u;
    unsigned wo = (tid >> 4) & 255u;
    unsigned ho = (tid >> 12) & 255u;
    unsigned n  = tid >> 20;

    // input float4 index: ((n*H + h)*W + w)*C4 + c4, with h=2*ho, w=2*wo
    unsigned ibase = ((n * H_ + 2u * ho) * W_ + 2u * wo) * C4 + c4;
    const unsigned ROW4 = W_ * C4;  // float4 per input row = 8192

    float4 a = in[ibase];
    float4 b = in[ibase + C4];
    float4 c = in[ibase + ROW4];
    float4 d = in[ibase + ROW4 + C4];

    float4 ll, lh, hl, hh;
    ll.x = 0.5f * ( a.x + b.x + c.x + d.x);
    ll.y = 0.5f * ( a.y + b.y + c.y + d.y);
    ll.z = 0.5f * ( a.z + b.z + c.z + d.z);
    ll.w = 0.5f * ( a.w + b.w + c.w + d.w);

    lh.x = 0.5f * (-a.x + b.x - c.x + d.x);
    lh.y = 0.5f * (-a.y + b.y - c.y + d.y);
    lh.z = 0.5f * (-a.z + b.z - c.z + d.z);
    lh.w = 0.5f * (-a.w + b.w - c.w + d.w);

    hl.x = 0.5f * (-a.x - b.x + c.x + d.x);
    hl.y = 0.5f * (-a.y - b.y + c.y + d.y);
    hl.z = 0.5f * (-a.z - b.z + c.z + d.z);
    hl.w = 0.5f * (-a.w - b.w + c.w + d.w);

    hh.x = 0.5f * ( a.x - b.x - c.x + d.x);
    hh.y = 0.5f * ( a.y - b.y - c.y + d.y);
    hh.z = 0.5f * ( a.z - b.z - c.z + d.z);
    hh.w = 0.5f * ( a.w - b.w - c.w + d.w);

    // output float4 index within a quadrant: ((n*HO + ho)*WO + wo)*C4 + c4
    unsigned o = ((n * HO + ho) * WO + wo) * C4 + c4;
    out[o]          = ll;
    out[o + Q4]     = lh;
    out[o + 2u*Q4]  = hl;
    out[o + 3u*Q4]  = hh;
}

extern "C" void kernel_launch(void* const* d_in, const int* in_sizes, int n_in,
                              void* d_out, int out_size)
{
    const float4* in  = (const float4*)d_in[0];
    float4*       out = (float4*)d_out;

    const unsigned total = Q4;             // 8,388,608 threads
    const unsigned block = 256;
    const unsigned grid  = total / block;  // 32768
    wavelet_pool_kernel<<<grid, block>>>(in, out);
}

// round 8
// speedup vs baseline: 1.0092x; 1.0092x over previous
#include <cuda_runtime.h>

// WaveLetPooling: input (8, 512, 512, 64) fp32 NHWC.
// Output: [ll | lh | hl | hh], each (8, 256, 256, 64), concatenated in d_out.
//
// 256-bit access variant: each thread handles TWO ADJACENT c4 slots
// (32 contiguous bytes per stream), letting ptxas emit LDG.E.256 /
// STG.E.256 (sm_10x-only). Same minimal traffic, half the LSU
// instructions and L1tex wavefronts per byte.

#define N_  8u
#define H_  512u
#define W_  512u
#define C_  64u
#define HO  (H_/2u)       // 256
#define WO  (W_/2u)       // 256
#define C8  (C_/8u)       // 8 float8-groups per position
#define Q4  (N_*HO*WO*(C_/4u)) // float4 per quadrant = 8,388,608

struct __align__(32) f8 { float4 lo, hi; };

__device__ __forceinline__ f8 haar8(const f8& a, const f8& b,
                                    const f8& c, const f8& d,
                                    float sa, float sb, float sc)
{
    f8 r;
    r.lo.x = 0.5f * (sa*a.lo.x + sb*b.lo.x + sc*c.lo.x + d.lo.x);
    r.lo.y = 0.5f * (sa*a.lo.y + sb*b.lo.y + sc*c.lo.y + d.lo.y);
    r.lo.z = 0.5f * (sa*a.lo.z + sb*b.lo.z + sc*c.lo.z + d.lo.z);
    r.lo.w = 0.5f * (sa*a.lo.w + sb*b.lo.w + sc*c.lo.w + d.lo.w);
    r.hi.x = 0.5f * (sa*a.hi.x + sb*b.hi.x + sc*c.hi.x + d.hi.x);
    r.hi.y = 0.5f * (sa*a.hi.y + sb*b.hi.y + sc*c.hi.y + d.hi.y);
    r.hi.z = 0.5f * (sa*a.hi.z + sb*b.hi.z + sc*c.hi.z + d.hi.z);
    r.hi.w = 0.5f * (sa*a.hi.w + sb*b.hi.w + sc*c.hi.w + d.hi.w);
    return r;
}

__global__ __launch_bounds__(256) void wavelet_pool_kernel(
    const f8* __restrict__ in, f8* __restrict__ out)
{
    unsigned tid = blockIdx.x * blockDim.x + threadIdx.x;
    // tid -> (n, ho, wo, c8): c8 in [0,8), wo in [0,256), ho in [0,256), n in [0,8)
    unsigned c8 = tid & 7u;
    unsigned wo = (tid >> 3) & 255u;
    unsigned ho = (tid >> 11) & 255u;
    unsigned n  = tid >> 19;

    // input f8 index: ((n*H + 2*ho)*W + 2*wo)*C8 + c8
    unsigned ibase = ((n * H_ + 2u * ho) * W_ + 2u * wo) * C8 + c8;
    const unsigned ROW8 = W_ * C8;  // f8 per input row = 4096

    f8 a = in[ibase];
    f8 b = in[ibase + C8];
    f8 c = in[ibase + ROW8];
    f8 d = in[ibase + ROW8 + C8];

    f8 ll = haar8(a, b, c, d,  1.f,  1.f,  1.f);
    f8 lh = haar8(a, b, c, d, -1.f,  1.f, -1.f);
    f8 hl = haar8(a, b, c, d, -1.f, -1.f,  1.f);
    f8 hh = haar8(a, b, c, d,  1.f, -1.f, -1.f);

    const unsigned Q8 = Q4 / 2u;  // f8 per quadrant = 4,194,304
    unsigned o = ((n * HO + ho) * WO + wo) * C8 + c8;
    out[o]          = ll;
    out[o + Q8]     = lh;
    out[o + 2u*Q8]  = hl;
    out[o + 3u*Q8]  = hh;
}

extern "C" void kernel_launch(void* const* d_in, const int* in_sizes, int n_in,
                              void* d_out, int out_size)
{
    const f8* in  = (const f8*)d_in[0];
    f8*       out = (f8*)d_out;

    const unsigned total = Q4 / 2u;        // 4,194,304 threads
    const unsigned block = 256;
    const unsigned grid  = total / block;  // 16384
    wavelet_pool_kernel<<<grid, block>>>(in, out);
}